// round 8
// baseline (speedup 1.0000x reference)
#include <cuda_runtime.h>
#include <cstdint>

// WholeMask R8: TMA bulk-store experiment.
// All register-store kernels pin at dur=26.6us with no saturated counter ->
// test whether the SM->L1->L2 store path is the hidden limiter by bypassing
// it: build the 29x512 row canvas (28 expanded mask rows + zero row) in SMEM,
// then emit each of the 256 output rows with one cp.async.bulk (2KB) store.
// One instruction per 2KB instead of 128; no warps needed to hide latency.

#define MH 28
#define MW 28
#define IMG 512
#define ROW_F 512
#define ROW_BYTES (ROW_F * 4)
#define CANVAS_ROWS 29
// canvas (29*2048) + soffb (512 ints)
#define SMEM_BYTES (CANVAS_ROWS * ROW_BYTES + IMG * 4)   // 61440

__global__ __launch_bounds__(256, 3)
void wholemask_kernel(const float* __restrict__ bboxess,
                      const int*   __restrict__ counts,
                      const float* __restrict__ maskss,
                      float*       __restrict__ out,
                      int Kk)
{
    extern __shared__ float sm[];
    float* canvas = sm;                                  // [29][512]
    int*   soffb  = (int*)(sm + CANVAS_ROWS * ROW_F);    // [512] byte offsets

    const int slice = blockIdx.x;              // b*K + k
    const int b = slice / Kk;
    const int k = slice - b * Kk;
    const int tid = threadIdx.x;               // 0..255

    const bool valid = (k < counts[b]);

    // Rounded (half-even == jnp.round) + clipped box.
    const float4 bb = reinterpret_cast<const float4*>(bboxess)[slice];
    int y1 = __float2int_rn(bb.x);
    int x1 = __float2int_rn(bb.y);
    int y2 = __float2int_rn(bb.z);
    int x2 = __float2int_rn(bb.w);
    y1 = min(max(y1, 0), IMG - 1);
    x1 = min(max(x1, 0), IMG - 1);
    y2 = min(max(y2, y1 + 1), IMG);
    x2 = min(max(x2, x1 + 1), IMG);
    const int h = y2 - y1;
    const int w = x2 - x1;

    // ---- Setup: canvas + row-offset LUT ----
    const float* gm = maskss + (size_t)slice * (MH * MW);

    // Row LUT: byte offset of source canvas row for each output y.
    for (int y = tid; y < IMG; y += 256) {
        const bool iny = valid && (y >= y1) && (y < y2);
        int sy = (y - y1) * MH / h;            // y>=y1 inside -> trunc==floor
        sy = min(max(sy, 0), MH - 1);
        soffb[y] = (iny ? sy : MH) * ROW_BYTES;
    }
    // Canvas rows 0..27: expanded mask with x-predication baked in.
    for (int i = tid; i < MH * ROW_F; i += 256) {
        const int r = i >> 9;                  // / 512
        const int x = i & (ROW_F - 1);
        const bool inx = valid && (x >= x1) && (x < x2);
        int sx = (x - x1) * MW / w;
        sx = min(max(sx, 0), MW - 1);
        canvas[i] = inx ? gm[r * MW + sx] : 0.0f;
    }
    // Zero row (row 28).
    for (int x = tid; x < ROW_F; x += 256)
        canvas[MH * ROW_F + x] = 0.0f;

    // Generic-proxy SMEM writes must be visible to the async proxy.
    asm volatile("fence.proxy.async.shared::cta;" ::: "memory");
    __syncthreads();

    // ---- Main: one TMA bulk store per output row ----
    const int ybase = blockIdx.y * 256;
    const int y = ybase + tid;                 // this thread's output row

    uint32_t sbase;
    asm("{ .reg .u64 t; cvta.to.shared.u64 t, %1; cvt.u32.u64 %0, t; }"
        : "=r"(sbase) : "l"(canvas));
    const uint32_t saddr = sbase + (uint32_t)soffb[y];
    float* gptr = out + (size_t)slice * (IMG * IMG) + (size_t)y * IMG;

    asm volatile(
        "cp.async.bulk.global.shared::cta.bulk_group [%0], [%1], %2;"
        :: "l"(gptr), "r"(saddr), "n"(ROW_BYTES) : "memory");
    asm volatile("cp.async.bulk.commit_group;" ::: "memory");
    // Guarantee stores are visible before kernel end.
    asm volatile("cp.async.bulk.wait_group 0;" ::: "memory");
}

extern "C" void kernel_launch(void* const* d_in, const int* in_sizes, int n_in,
                              void* d_out, int out_size)
{
    const float* bboxess = (const float*)d_in[0];   // (B,K,4) f32
    const int*   counts  = (const int*)  d_in[1];   // (B,1)   i32
    const float* maskss  = (const float*)d_in[2];   // (B,K,1,28,28) f32

    const int BK = in_sizes[0] / 4;                 // B*K
    const int Bv = in_sizes[1];                     // B
    const int Kk = BK / Bv;                         // K

    cudaFuncSetAttribute(wholemask_kernel,
                         cudaFuncAttributeMaxDynamicSharedMemorySize, SMEM_BYTES);

    dim3 block(256);
    dim3 grid(BK, 2);              // 128 slices x 2 halves = 256 CTAs
    wholemask_kernel<<<grid, block, SMEM_BYTES>>>(bboxess, counts, maskss,
                                                  (float*)d_out, Kk);
}

// round 9
// speedup vs baseline: 1.0588x; 1.0588x over previous
#include <cuda_runtime.h>
#include <cstdint>

// WholeMask R9: memset + box-painter.
// Discriminator: let the driver's memset path do the 134MB zero-fill (its
// streaming-write rate is the machine's upper bound), then paint only the
// box interiors (~3-4MB) with predicated float4 stores. If driver memset
// beats my kernels' ~5.5TB/s, this wins; if not, the chip wall is confirmed.

#define MH 28
#define MW 28
#define IMG 512

__global__ __launch_bounds__(256, 8)
void box_paint_kernel(const float* __restrict__ bboxess,
                      const int*   __restrict__ counts,
                      const float* __restrict__ maskss,
                      float*       __restrict__ out,
                      int Kk)
{
    __shared__ float         smask[MH * MW];   // 3136 B
    __shared__ unsigned char ssx[IMG];         // sx per x (valid inside box)

    const int slice = blockIdx.x;              // b*K + k
    const int b = slice / Kk;
    const int k = slice - b * Kk;
    const int tid = threadIdx.x;               // 0..255

    if (k >= counts[b]) return;                // block-uniform: whole CTA exits

    // Rounded (half-even == jnp.round) + clipped box.
    const float4 bb = reinterpret_cast<const float4*>(bboxess)[slice];
    int y1 = __float2int_rn(bb.x);
    int x1 = __float2int_rn(bb.y);
    int y2 = __float2int_rn(bb.z);
    int x2 = __float2int_rn(bb.w);
    y1 = min(max(y1, 0), IMG - 1);
    x1 = min(max(x1, 0), IMG - 1);
    y2 = min(max(y2, y1 + 1), IMG);
    x2 = min(max(x2, x1 + 1), IMG);
    const int h = y2 - y1;
    const int w = x2 - x1;

    // ---- Setup ----
    {
        const float* gm = maskss + (size_t)slice * (MH * MW);
        for (int i = tid; i < MH * MW; i += 256)
            smask[i] = gm[i];
        for (int x = tid; x < IMG; x += 256) {
            int sx = (x - x1) * MW / w;        // valid for x>=x1 (trunc==floor)
            ssx[x] = (unsigned char)min(max(sx, 0), MW - 1);
        }
    }
    __syncthreads();

    const int lane = tid & 31;
    const int wrp  = tid >> 5;                 // 0..7
    const int xa   = x1 & ~3;                  // 16B-aligned span start

    float* obase = out + (size_t)slice * (IMG * IMG);

    // Each warp paints rows y1+wrp, y1+wrp+8, ... ; lanes cover the x-span
    // in float4 quads. Out-of-box lanes write 0 over memset zeros (harmless).
    for (int r = wrp; r < h; r += 8) {
        const int y = y1 + r;
        int sy = r * MH / h;
        sy = min(sy, MH - 1);
        const float* mrow = smask + sy * MW;
        float* orow = obase + (size_t)y * IMG;

        for (int xq = xa + lane * 4; xq < x2; xq += 128) {
            float4 v;
            v.x = (xq     >= x1 && xq     < x2) ? mrow[ssx[xq]]     : 0.f;
            v.y = (xq + 1 >= x1 && xq + 1 < x2) ? mrow[ssx[xq + 1]] : 0.f;
            v.z = (xq + 2 >= x1 && xq + 2 < x2) ? mrow[ssx[xq + 2]] : 0.f;
            v.w = (xq + 3 >= x1 && xq + 3 < x2) ? mrow[ssx[xq + 3]] : 0.f;
            *reinterpret_cast<float4*>(orow + xq) = v;
        }
    }
}

extern "C" void kernel_launch(void* const* d_in, const int* in_sizes, int n_in,
                              void* d_out, int out_size)
{
    const float* bboxess = (const float*)d_in[0];   // (B,K,4) f32
    const int*   counts  = (const int*)  d_in[1];   // (B,1)   i32
    const float* maskss  = (const float*)d_in[2];   // (B,K,1,28,28) f32

    const int BK = in_sizes[0] / 4;                 // B*K
    const int Bv = in_sizes[1];                     // B
    const int Kk = BK / Bv;                         // K

    // Zero-fill via driver memset (graph memset node; bit pattern 0 == 0.0f).
    cudaMemsetAsync(d_out, 0, (size_t)out_size * sizeof(float), 0);

    // Paint box interiors only (~3-4 MB total).
    box_paint_kernel<<<BK, 256>>>(bboxess, counts, maskss,
                                  (float*)d_out, Kk);
}

// round 10
// speedup vs baseline: 1.2000x; 1.1333x over previous
#include <cuda_runtime.h>
#include <cstdint>

// WholeMask R10: CE-memset zero-fill + minimal box painter.
// R9 evidence: driver memset writes 134MB @ ~6.7TB/s (~20us), faster than any
// SM store loop measured (~5.5TB/s). Keep memset for the bulk zero-fill and
// shrink the paint kernel to ~2-3us: 1024 CTAs (slice x 8 row-groups),
// u8 LUTs for sy/sx (divisions in setup only), warp-strided rows.

#define MH 28
#define MW 28
#define IMG 512

__global__ __launch_bounds__(128, 12)
void box_paint_kernel(const float* __restrict__ bboxess,
                      const int*   __restrict__ counts,
                      const float* __restrict__ maskss,
                      float*       __restrict__ out,
                      int Kk)
{
    __shared__ float         smask[MH * MW];   // 3136 B
    __shared__ unsigned char ssy[IMG];         // sy per box-row r (r < h)
    __shared__ unsigned char ssx[IMG];         // sx per x (valid in box)

    const int slice = blockIdx.x;              // b*K + k
    const int b = slice / Kk;
    const int k = slice - b * Kk;
    const int tid = threadIdx.x;               // 0..127

    if (k >= counts[b]) return;                // block-uniform exit

    // Rounded (half-even == jnp.round) + clipped box.
    const float4 bb = reinterpret_cast<const float4*>(bboxess)[slice];
    int y1 = __float2int_rn(bb.x);
    int x1 = __float2int_rn(bb.y);
    int y2 = __float2int_rn(bb.z);
    int x2 = __float2int_rn(bb.w);
    y1 = min(max(y1, 0), IMG - 1);
    x1 = min(max(x1, 0), IMG - 1);
    y2 = min(max(y2, y1 + 1), IMG);
    x2 = min(max(x2, x1 + 1), IMG);
    const int h = y2 - y1;
    const int w = x2 - x1;

    // ---- Setup: mask tile + LUTs (all divisions here) ----
    {
        const float* gm = maskss + (size_t)slice * (MH * MW);
        for (int i = tid; i < MH * MW; i += 128)
            smask[i] = gm[i];
        for (int p = tid; p < IMG; p += 128) {
            int sy = p * MH / h;               // valid for p < h
            ssy[p] = (unsigned char)min(sy, MH - 1);
            int sx = (p - x1) * MW / w;        // valid for p >= x1
            ssx[p] = (unsigned char)min(max(sx, 0), MW - 1);
        }
    }
    __syncthreads();

    const int lane = tid & 31;
    const int wrp  = tid >> 5;                 // 0..3
    const int g    = blockIdx.y * 4 + wrp;     // global warp id 0..31 per slice
    const int xa   = x1 & ~3;                  // aligned span start

    float* obase = out + (size_t)slice * (IMG * IMG);

    // Rows r = g, g+32, ... within box; lanes cover x-span in float4 quads.
    for (int r = g; r < h; r += 32) {
        const int y = y1 + r;
        const float* mrow = smask + (int)ssy[r] * MW;
        float* orow = obase + (size_t)y * IMG;

        for (int xq = xa + lane * 4; xq < x2; xq += 128) {
            float4 v;
            v.x = (xq     >= x1 && xq     < x2) ? mrow[ssx[xq]]     : 0.f;
            v.y = (xq + 1 >= x1 && xq + 1 < x2) ? mrow[ssx[xq + 1]] : 0.f;
            v.z = (xq + 2 >= x1 && xq + 2 < x2) ? mrow[ssx[xq + 2]] : 0.f;
            v.w = (xq + 3 >= x1 && xq + 3 < x2) ? mrow[ssx[xq + 3]] : 0.f;
            *reinterpret_cast<float4*>(orow + xq) = v;   // zeros over zeros OK
        }
    }
}

extern "C" void kernel_launch(void* const* d_in, const int* in_sizes, int n_in,
                              void* d_out, int out_size)
{
    const float* bboxess = (const float*)d_in[0];   // (B,K,4) f32
    const int*   counts  = (const int*)  d_in[1];   // (B,1)   i32
    const float* maskss  = (const float*)d_in[2];   // (B,K,1,28,28) f32

    const int BK = in_sizes[0] / 4;                 // B*K
    const int Bv = in_sizes[1];                     // B
    const int Kk = BK / Bv;                         // K

    // Bulk zero-fill via driver/CE memset (graph memset node, ~6.7 TB/s).
    cudaMemsetAsync(d_out, 0, (size_t)out_size * sizeof(float), 0);

    // Paint only box interiors (~3 MB).
    dim3 block(128);
    dim3 grid(BK, 8);              // 1024 CTAs
    box_paint_kernel<<<grid, block>>>(bboxess, counts, maskss,
                                      (float*)d_out, Kk);
}